// round 13
// baseline (speedup 1.0000x reference)
#include <cuda_runtime.h>
#include <cuda_fp16.h>
#include <cstdint>

#define KC   512
#define DD   64
#define HW   4096
#define NB   32
#define NPIX (NB * HW)
#define XNUM (NPIX * DD)

#define TILE_M  64
#define NTILES  (NPIX / TILE_M)   // 2048

__device__ double   g_losssum;
__device__ float    g_wsq[KC];
__device__ uint32_t g_wh2[KC * 32];   // prepacked, fragment-permuted half2 words
__device__ int      g_flag[NPIX];
__device__ int      g_nflag;
__device__ int      g_done;

// smem byte map for the filter kernel
#define W2_OFF   0                         // [512][36] half2 words = 73728 B
#define X_OFF    73728                     // [64][36] half2 words  = 9216 B
#define WSQ_OFF  82944                     // [512] f32
#define S1_OFF   84992                     // [4][64] f32
#define RB_OFF   86016                     // [2][64] f32
#define RS_OFF   86528                     // [2][64] f32
#define RI_OFF   87040                     // [2][64] i32
#define SM_TOT   87552

__device__ __forceinline__ void mma_f16(float& c0, float& c1, float& c2, float& c3,
                                        uint32_t a0, uint32_t a1, uint32_t a2, uint32_t a3,
                                        uint32_t b0, uint32_t b1) {
    asm volatile(
        "mma.sync.aligned.m16n8k16.row.col.f32.f16.f16.f32 "
        "{%0,%1,%2,%3}, {%4,%5,%6,%7}, {%8,%9}, {%0,%1,%2,%3};"
        : "+f"(c0), "+f"(c1), "+f"(c2), "+f"(c3)
        : "r"(a0), "r"(a1), "r"(a2), "r"(a3), "r"(b0), "r"(b1));
}
__device__ __forceinline__ uint32_t packh2(float lo, float hi) {
    const __half2 h = __floats2half2_rn(lo, hi);
    return *(const uint32_t*)&h;
}

// Reference fp32 reduction tree for 64 elements (vec=2 + butterfly).
__device__ __forceinline__ float sumsq_tree64(const float* v) {
    float p[32];
#pragma unroll
    for (int t = 0; t < 32; t++) {
        float a = __fmul_rn(v[2 * t], v[2 * t]);
        float b = __fmul_rn(v[2 * t + 1], v[2 * t + 1]);
        p[t] = __fadd_rn(a, b);
    }
#pragma unroll
    for (int off = 16; off >= 1; off >>= 1)
#pragma unroll
        for (int l = 0; l < 16; l++)
            if (l < off) p[l] = __fadd_rn(p[l], p[l + off]);
    return p[0];
}

// ---------------------------------------------------------------------------
// K1: wsq (bit-exact tree), fragment-permuted packed codebook, flag reset.
// Permutation: dst word = tI*8 + kk*2 + h  <->  src word j = 8*kk + tI + 4*h
// so one uint4 load yields (b0,b1) for two consecutive k-steps.
// ---------------------------------------------------------------------------
__global__ void vq_prep(const float* __restrict__ w)
{
    const int k = threadIdx.x;
    if (k < KC) {
        float v[DD];
#pragma unroll
        for (int d = 0; d < DD; d++) v[d] = w[k * DD + d];
        g_wsq[k] = sumsq_tree64(v);
#pragma unroll
        for (int dst = 0; dst < 32; dst++) {
            const int tI = dst >> 3, kk = (dst & 7) >> 1, h = dst & 1;
            const int j  = 8 * kk + tI + 4 * h;
            g_wh2[k * 32 + dst] = packh2(v[2 * j], v[2 * j + 1]);
        }
    }
    if (k == 0) g_nflag = 0;
}

// ---------------------------------------------------------------------------
// K2: fp16 MMA filter (LDS.128 B-fragments) + fused enc zero + fused scatter.
// Block = 256 thr = 8 warps; warps 0-3: 64px x codes[0,256); warps 4-7:
// 64px x codes[256,512). Tile = 64 pixels.
// ---------------------------------------------------------------------------
__global__ void __launch_bounds__(256, 2)
vq_mma_filter(const float* __restrict__ x, const float* __restrict__ w,
              float* __restrict__ out_idx, float* __restrict__ out_q,
              float* __restrict__ out_enc, double* __restrict__ losssum)
{
    extern __shared__ char smc[];
    uint32_t* w2    = (uint32_t*)(smc + W2_OFF);
    uint32_t* x_s   = (uint32_t*)(smc + X_OFF);
    float*    wsq_s = (float*)(smc + WSQ_OFF);
    float*    s1h   = (float*)(smc + S1_OFF);    // [4][64]
    float*    rb    = (float*)(smc + RB_OFF);    // [2][64]
    float*    rs    = (float*)(smc + RS_OFF);
    int*      ri    = (int*)(smc + RI_OFF);

    const int tid = threadIdx.x;
    const int n0  = blockIdx.x * TILE_M;
    const int b   = n0 >> 12;
    const int hw0 = n0 & 4095;

    // ---- codebook copy (prepacked, contiguous src -> stride-36 rows)
    {
        const uint4* src = (const uint4*)g_wh2;     // 4096 uint4
        for (int i = tid; i < 4096; i += 256) {
            const int k = i >> 3, q4 = i & 7;
            *(uint4*)&w2[k * 36 + q4 * 4] = src[i];
        }
        for (int i = tid; i < KC; i += 256) wsq_s[i] = g_wsq[i];
    }
    // ---- x tile: thread (p = tid&63, h = tid>>6) fills words [8h, 8h+8)
    {
        const float* xg = x + (size_t)b * DD * HW + hw0;
        const int p = tid & 63, h = tid >> 6;
        float s1 = 0.f;
#pragma unroll
        for (int j2 = 0; j2 < 8; j2++) {
            const int j = 8 * h + j2, d = 2 * j;
            const float v0 = xg[(size_t)d * HW + p];
            const float v1 = xg[(size_t)(d + 1) * HW + p];
            s1 += fabsf(v0) + fabsf(v1);
            x_s[p * 36 + j] = packh2(v0, v1);
        }
        s1h[h * 64 + p] = s1;
    }
    // ---- fused enc zero-fill for rows n0..n0+63 (aligned-peeled float4)
    {
        float* encb = out_enc + (size_t)n0 * KC;
        const unsigned mis = (unsigned)((unsigned long long)(uintptr_t)encb & 15ull);
        const int head  = (int)(((16u - mis) & 15u) >> 2);
        float4*  ez     = (float4*)(encb + head);
        const int body4 = (TILE_M * KC - head) >> 2;
        const int tail  = (TILE_M * KC - head) & 3;
        if (tid == 0) {
            for (int i = 0; i < head; i++) encb[i] = 0.f;
            for (int i = 0; i < tail; i++) encb[head + body4 * 4 + i] = 0.f;
        }
        const float4 z4 = make_float4(0.f, 0.f, 0.f, 0.f);
        for (int i = tid; i < body4; i += 256) ez[i] = z4;
    }
    __syncthreads();

    // ---- per-warp MMA: 16 pixels x 256 codes
    const int lane = tid & 31, wid = tid >> 5;
    const int gid  = lane >> 2, tI = lane & 3;
    const int pwid = wid & 3, half = wid >> 2;
    const int koff = half * 256;
    const int r0   = pwid * 16 + gid, r1 = r0 + 8;

    uint32_t A[4][4];
#pragma unroll
    for (int kk = 0; kk < 4; kk++) {
        A[kk][0] = x_s[r0 * 36 + 8 * kk + tI];
        A[kk][1] = x_s[r1 * 36 + 8 * kk + tI];
        A[kk][2] = x_s[r0 * 36 + 8 * kk + tI + 4];
        A[kk][3] = x_s[r1 * 36 + 8 * kk + tI + 4];
    }

    float best0 = 3.4e38f, sec0 = 3.4e38f, best1 = 3.4e38f, sec1 = 3.4e38f;
    int   bi0 = 0, bi1 = 0;

#pragma unroll 1
    for (int nt = 0; nt < 32; nt += 4) {
        float c[4][4];
#pragma unroll
        for (int q = 0; q < 4; q++)
#pragma unroll
            for (int f = 0; f < 4; f++) c[q][f] = 0.f;

#pragma unroll
        for (int q = 0; q < 4; q++) {
            const int row = koff + (nt + q) * 8 + gid;
            const uint4 B0 = *(const uint4*)&w2[row * 36 + tI * 8];
            const uint4 B1 = *(const uint4*)&w2[row * 36 + tI * 8 + 4];
            mma_f16(c[q][0], c[q][1], c[q][2], c[q][3],
                    A[0][0], A[0][1], A[0][2], A[0][3], B0.x, B0.y);
            mma_f16(c[q][0], c[q][1], c[q][2], c[q][3],
                    A[1][0], A[1][1], A[1][2], A[1][3], B0.z, B0.w);
            mma_f16(c[q][0], c[q][1], c[q][2], c[q][3],
                    A[2][0], A[2][1], A[2][2], A[2][3], B1.x, B1.y);
            mma_f16(c[q][0], c[q][1], c[q][2], c[q][3],
                    A[3][0], A[3][1], A[3][2], A[3][3], B1.z, B1.w);
        }
#pragma unroll
        for (int q = 0; q < 4; q++) {
            const int cb = koff + (nt + q) * 8 + 2 * tI;
            const float w0 = wsq_s[cb], w1 = wsq_s[cb + 1];
            const float d00 = __fmaf_rn(-2.f, c[q][0], w0);
            const float d01 = __fmaf_rn(-2.f, c[q][1], w1);
            const float d10 = __fmaf_rn(-2.f, c[q][2], w0);
            const float d11 = __fmaf_rn(-2.f, c[q][3], w1);
            if (d00 < best0) { sec0 = best0; best0 = d00; bi0 = cb; }
            else if (d00 < sec0) sec0 = d00;
            if (d01 < best0) { sec0 = best0; best0 = d01; bi0 = cb + 1; }
            else if (d01 < sec0) sec0 = d01;
            if (d10 < best1) { sec1 = best1; best1 = d10; bi1 = cb; }
            else if (d10 < sec1) sec1 = d10;
            if (d11 < best1) { sec1 = best1; best1 = d11; bi1 = cb + 1; }
            else if (d11 < sec1) sec1 = d11;
        }
    }

    // merge top-2 across the 4 threads of each quad (butterfly xor 1, 2)
#pragma unroll
    for (int m = 1; m <= 2; m <<= 1) {
        float ob = __shfl_xor_sync(0xffffffffu, best0, m);
        float os = __shfl_xor_sync(0xffffffffu, sec0,  m);
        int  obi = __shfl_xor_sync(0xffffffffu, bi0,   m);
        if (ob < best0 || (ob == best0 && obi < bi0)) { sec0 = fminf(best0, os); best0 = ob; bi0 = obi; }
        else sec0 = fminf(sec0, ob);
        ob  = __shfl_xor_sync(0xffffffffu, best1, m);
        os  = __shfl_xor_sync(0xffffffffu, sec1,  m);
        obi = __shfl_xor_sync(0xffffffffu, bi1,   m);
        if (ob < best1 || (ob == best1 && obi < bi1)) { sec1 = fminf(best1, os); best1 = ob; bi1 = obi; }
        else sec1 = fminf(sec1, ob);
    }
    if (tI == 0) {
        rb[half * 64 + r0] = best0; rs[half * 64 + r0] = sec0; ri[half * 64 + r0] = bi0;
        rb[half * 64 + r1] = best1; rs[half * 64 + r1] = sec1; ri[half * 64 + r1] = bi1;
    }
    __syncthreads();

    // ---- combine code-halves, flag, publish (reuse x area for res arrays)
    int* res_i = (int*)(smc + X_OFF);
    int* res_f = (int*)(smc + X_OFF + 256);
    if (tid < TILE_M) {
        const int p = tid;
        const float b1v = rb[p],     s1v = rs[p];
        const float b2v = rb[64 + p], s2v = rs[64 + p];
        const int   i1v = ri[p],     i2v = ri[64 + p];
        float bb, ss; int ii;
        if (b2v < b1v || (b2v == b1v && i2v < i1v)) { bb = b2v; ii = i2v; }
        else { bb = b1v; ii = i1v; }
        ss = fminf(fminf(s1v, s2v), fmaxf(b1v, b2v));

        out_idx[n0 + p] = (float)ii;
        res_i[p] = ii;

        const float S1 = s1h[p] + s1h[64 + p] + s1h[128 + p] + s1h[192 + p];
        const bool flag = (__fsub_rn(ss, bb) < __fmaf_rn(1e-5f, S1, 4e-5f));
        res_f[p] = flag;
        const unsigned m = __ballot_sync(0xffffffffu, flag);
        if (m) {
            const int lane2 = tid & 31;
            const int leader = __ffs(m) - 1;
            int base = 0;
            if (lane2 == leader) base = atomicAdd(&g_nflag, __popc(m));
            base = __shfl_sync(0xffffffffu, base, leader);
            if (flag) g_flag[base + __popc(m & ((1u << lane2) - 1u))] = n0 + p;
        }
    }
    __syncthreads();

    // ---- fused scatter: threads 0..127, two threads per pixel (32 dims each)
    float s = 0.f;
    if (tid < 2 * TILE_M) {
        const int p  = tid >> 1;
        const int dh = (tid & 1) * 32;
        if (!res_f[p]) {
            const int n  = n0 + p;
            const int ii = res_i[p];
            const float*  xp = x     + (size_t)b * DD * HW + hw0 + p;
            float*        qp = out_q + (size_t)b * DD * HW + hw0 + p;
            const float4* wr = (const float4*)(w + (size_t)ii * DD + dh);
#pragma unroll
            for (int j = 0; j < 8; j++) {
                const float4 wv = __ldg(wr + j);
                const int d0i = dh + 4 * j;
                const float xv0 = xp[(size_t)(d0i + 0) * HW];
                const float xv1 = xp[(size_t)(d0i + 1) * HW];
                const float xv2 = xp[(size_t)(d0i + 2) * HW];
                const float xv3 = xp[(size_t)(d0i + 3) * HW];
                const float d0 = __fsub_rn(wv.x, xv0);
                const float d1 = __fsub_rn(wv.y, xv1);
                const float d2 = __fsub_rn(wv.z, xv2);
                const float d3 = __fsub_rn(wv.w, xv3);
                qp[(size_t)(d0i + 0) * HW] = __fadd_rn(xv0, d0);
                qp[(size_t)(d0i + 1) * HW] = __fadd_rn(xv1, d1);
                qp[(size_t)(d0i + 2) * HW] = __fadd_rn(xv2, d2);
                qp[(size_t)(d0i + 3) * HW] = __fadd_rn(xv3, d3);
                s = fmaf(d0, d0, s); s = fmaf(d1, d1, s);
                s = fmaf(d2, d2, s); s = fmaf(d3, d3, s);
            }
            if ((tid & 1) == 0) out_enc[(size_t)n * KC + ii] = 1.0f;
        }
    }
#pragma unroll
    for (int off = 16; off; off >>= 1) s += __shfl_down_sync(0xffffffffu, s, off);
    __shared__ float sred[8];
    if ((tid & 31) == 0) sred[tid >> 5] = s;
    __syncthreads();
    if (tid < 8) {
        float v = sred[tid];
#pragma unroll
        for (int off = 4; off; off >>= 1) v += __shfl_down_sync(0xffu, v, off);
        if (tid == 0 && v != 0.f) atomicAdd(losssum, (double)v);
    }
}

// ---------------------------------------------------------------------------
// K3: bit-exact fallback for flagged pixels (1 warp per pixel) + their
// q / enc / loss, plus fused loss finalize via done-counter.
// ---------------------------------------------------------------------------
__global__ void __launch_bounds__(256, 1)
vq_fallback(const float* __restrict__ x, const float* __restrict__ w,
            float* __restrict__ out_idx, float* __restrict__ out_q,
            float* __restrict__ out_enc, double* __restrict__ losssum,
            float* __restrict__ out_loss)
{
    extern __shared__ char smc[];
    float* w_s   = (float*)smc;                          // [512*65] padded
    float* wsq_s = (float*)(smc + KC * 65 * 4);          // [512]
    float* xrow  = (float*)(smc + KC * 65 * 4 + KC * 4); // [8][64]
    const int tid = threadIdx.x, wid = tid >> 5, lane = tid & 31;
    const int nflag = g_nflag;

    if (blockIdx.x * 8 < nflag) {
        for (int i = tid; i < KC * DD; i += 256) {
            const int k = i >> 6, d = i & 63;
            w_s[k * 65 + d] = w[i];
        }
        for (int i = tid; i < KC; i += 256) wsq_s[i] = g_wsq[i];
        __syncthreads();

        for (int f = blockIdx.x * 8 + wid; f < nflag; f += gridDim.x * 8) {
            const int n  = g_flag[f];
            const int b  = n >> 12, hw = n & 4095;
            const float* xp = x + (size_t)b * DD * HW + hw;
            xrow[wid * 64 + lane]      = xp[(size_t)lane * HW];
            xrow[wid * 64 + lane + 32] = xp[(size_t)(lane + 32) * HW];
            __syncwarp();
            float pa = __fmul_rn(xrow[wid * 64 + 2 * lane],     xrow[wid * 64 + 2 * lane]);
            float pb = __fmul_rn(xrow[wid * 64 + 2 * lane + 1], xrow[wid * 64 + 2 * lane + 1]);
            float pt = __fadd_rn(pa, pb);
#pragma unroll
            for (int off = 16; off >= 1; off >>= 1) {
                const float q = __shfl_down_sync(0xffffffffu, pt, off);
                pt = __fadd_rn(pt, q);
            }
            const float xsq = __shfl_sync(0xffffffffu, pt, 0);

            float bd = 3.4e38f; int bk = 0;
#pragma unroll 1
            for (int j = 0; j < 16; j++) {
                const int k = lane + 32 * j;
                float dot = 0.f;
#pragma unroll
                for (int d = 0; d < DD; d++)
                    dot = __fmaf_rn(xrow[wid * 64 + d], w_s[k * 65 + d], dot);
                const float dist = __fsub_rn(__fadd_rn(xsq, wsq_s[k]), __fadd_rn(dot, dot));
                if (dist < bd) { bd = dist; bk = k; }
            }
#pragma unroll
            for (int off = 16; off >= 1; off >>= 1) {
                const float od = __shfl_down_sync(0xffffffffu, bd, off);
                const int   ok = __shfl_down_sync(0xffffffffu, bk, off);
                if (od < bd || (od == bd && ok < bk)) { bd = od; bk = ok; }
            }
            bk = __shfl_sync(0xffffffffu, bk, 0);

            float* qp = out_q + (size_t)b * DD * HW + hw;
            const float xv0 = xrow[wid * 64 + lane];
            const float xv1 = xrow[wid * 64 + lane + 32];
            const float wv0 = w_s[bk * 65 + lane];
            const float wv1 = w_s[bk * 65 + lane + 32];
            const float d0  = __fsub_rn(wv0, xv0);
            const float d1  = __fsub_rn(wv1, xv1);
            qp[(size_t)lane * HW]        = __fadd_rn(xv0, d0);
            qp[(size_t)(lane + 32) * HW] = __fadd_rn(xv1, d1);
            float ls = fmaf(d1, d1, __fmul_rn(d0, d0));
#pragma unroll
            for (int off = 16; off >= 1; off >>= 1)
                ls += __shfl_down_sync(0xffffffffu, ls, off);
            if (lane == 0) {
                out_idx[n] = (float)bk;
                out_enc[(size_t)n * KC + bk] = 1.0f;
                atomicAdd(losssum, (double)ls);
            }
            __syncwarp();
        }
    }
    __syncthreads();
    // fused finalize: last block to finish computes the loss output
    if (tid == 0) {
        __threadfence();
        const int old = atomicAdd(&g_done, 1);
        if (old == (int)gridDim.x - 1) {
            __threadfence();
            out_loss[0] = (float)(2.0 * (*losssum) / (double)XNUM);
            g_done = 0;
        }
    }
}

// ---------------------------------------------------------------------------
extern "C" void kernel_launch(void* const* d_in, const int* in_sizes, int n_in,
                              void* d_out, int out_size)
{
    const float* x = (const float*)d_in[0];   // [32, 64, 64, 64] NCHW
    const float* w = (const float*)d_in[1];   // [512, 64]

    float* out      = (float*)d_out;
    float* out_loss = out;
    float* out_q    = out + 1;
    float* out_enc  = out + 1 + (size_t)XNUM;
    float* out_idx  = out + 1 + (size_t)XNUM + (size_t)NPIX * KC;

    double* loss_ptr = nullptr;
    cudaGetSymbolAddress((void**)&loss_ptr, g_losssum);

    const int smem_fb = KC * 65 * 4 + KC * 4 + 8 * DD * 4;
    cudaFuncSetAttribute(vq_mma_filter, cudaFuncAttributeMaxDynamicSharedMemorySize, SM_TOT);
    cudaFuncSetAttribute(vq_fallback,   cudaFuncAttributeMaxDynamicSharedMemorySize, smem_fb);

    cudaMemsetAsync(loss_ptr, 0, sizeof(double), 0);

    vq_prep      <<<1, 512>>>(w);
    vq_mma_filter<<<NTILES, 256, SM_TOT>>>(x, w, out_idx, out_q, out_enc, loss_ptr);
    vq_fallback  <<<128, 256, smem_fb>>>(x, w, out_idx, out_q, out_enc, loss_ptr, out_loss);
}

// round 14
// speedup vs baseline: 1.1025x; 1.1025x over previous
#include <cuda_runtime.h>
#include <cuda_fp16.h>
#include <cstdint>

#define KC   512
#define DD   64
#define HW   4096
#define NB   32
#define NPIX (NB * HW)
#define XNUM (NPIX * DD)

#define TILE_M  64
#define NTILES  (NPIX / TILE_M)   // 2048

__device__ double   g_losssum;
__device__ float    g_wsq[KC];
__device__ uint32_t g_wh2[KC * 32];   // prepacked, fragment-permuted half2 words
__device__ int      g_flag[NPIX];
__device__ int      g_nflag;
__device__ int      g_done;

// smem byte map for the filter kernel
#define W2_OFF   0                         // [512][36] half2 words = 73728 B
#define X_OFF    73728                     // [64][36] half2 words  = 9216 B
#define WSQ_OFF  82944                     // [512] f32
#define S1_OFF   84992                     // [4][64] f32
#define RB_OFF   86016                     // [2][64] f32
#define RS_OFF   86528                     // [2][64] f32
#define RI_OFF   87040                     // [2][64] i32
#define SM_TOT   87552

__device__ __forceinline__ void mma_f16(float& c0, float& c1, float& c2, float& c3,
                                        uint32_t a0, uint32_t a1, uint32_t a2, uint32_t a3,
                                        uint32_t b0, uint32_t b1) {
    asm volatile(
        "mma.sync.aligned.m16n8k16.row.col.f32.f16.f16.f32 "
        "{%0,%1,%2,%3}, {%4,%5,%6,%7}, {%8,%9}, {%0,%1,%2,%3};"
        : "+f"(c0), "+f"(c1), "+f"(c2), "+f"(c3)
        : "r"(a0), "r"(a1), "r"(a2), "r"(a3), "r"(b0), "r"(b1));
}
__device__ __forceinline__ uint32_t packh2(float lo, float hi) {
    const __half2 h = __floats2half2_rn(lo, hi);
    return *(const uint32_t*)&h;
}

// Reference fp32 reduction tree for 64 elements (vec=2 + butterfly).
__device__ __forceinline__ float sumsq_tree64(const float* v) {
    float p[32];
#pragma unroll
    for (int t = 0; t < 32; t++) {
        float a = __fmul_rn(v[2 * t], v[2 * t]);
        float b = __fmul_rn(v[2 * t + 1], v[2 * t + 1]);
        p[t] = __fadd_rn(a, b);
    }
#pragma unroll
    for (int off = 16; off >= 1; off >>= 1)
#pragma unroll
        for (int l = 0; l < 16; l++)
            if (l < off) p[l] = __fadd_rn(p[l], p[l + off]);
    return p[0];
}

// ---------------------------------------------------------------------------
// K1: wsq (bit-exact tree), fragment-permuted packed codebook, flag reset.
// PARALLELIZED: 8 blocks x 64 threads (one code per thread, 8 SMs).
// Permutation: dst word = tI*8 + kk*2 + h  <->  src word j = 8*kk + tI + 4*h
// ---------------------------------------------------------------------------
__global__ void __launch_bounds__(64, 8)
vq_prep(const float* __restrict__ w)
{
    const int k = blockIdx.x * 64 + threadIdx.x;
    if (k < KC) {
        float v[DD];
#pragma unroll
        for (int d = 0; d < DD; d++) v[d] = w[k * DD + d];
        g_wsq[k] = sumsq_tree64(v);
#pragma unroll
        for (int dst = 0; dst < 32; dst++) {
            const int tI = dst >> 3, kk = (dst & 7) >> 1, h = dst & 1;
            const int j  = 8 * kk + tI + 4 * h;
            g_wh2[k * 32 + dst] = packh2(v[2 * j], v[2 * j + 1]);
        }
    }
    if (k == 0) g_nflag = 0;
}

// ---------------------------------------------------------------------------
// K2: fp16 MMA filter (LDS.128 B-fragments) + fused enc zero + fused scatter.
// Block = 256 thr = 8 warps; warps 0-3: 64px x codes[0,256); warps 4-7:
// 64px x codes[256,512). Tile = 64 pixels.
// ---------------------------------------------------------------------------
__global__ void __launch_bounds__(256, 2)
vq_mma_filter(const float* __restrict__ x, const float* __restrict__ w,
              float* __restrict__ out_idx, float* __restrict__ out_q,
              float* __restrict__ out_enc, double* __restrict__ losssum)
{
    extern __shared__ char smc[];
    uint32_t* w2    = (uint32_t*)(smc + W2_OFF);
    uint32_t* x_s   = (uint32_t*)(smc + X_OFF);
    float*    wsq_s = (float*)(smc + WSQ_OFF);
    float*    s1h   = (float*)(smc + S1_OFF);    // [4][64]
    float*    rb    = (float*)(smc + RB_OFF);    // [2][64]
    float*    rs    = (float*)(smc + RS_OFF);
    int*      ri    = (int*)(smc + RI_OFF);

    const int tid = threadIdx.x;
    const int n0  = blockIdx.x * TILE_M;
    const int b   = n0 >> 12;
    const int hw0 = n0 & 4095;

    // ---- codebook copy (prepacked, contiguous src -> stride-36 rows)
    {
        const uint4* src = (const uint4*)g_wh2;     // 4096 uint4
        for (int i = tid; i < 4096; i += 256) {
            const int k = i >> 3, q4 = i & 7;
            *(uint4*)&w2[k * 36 + q4 * 4] = src[i];
        }
        for (int i = tid; i < KC; i += 256) wsq_s[i] = g_wsq[i];
    }
    // ---- x tile: thread (p = tid&63, h = tid>>6) fills words [8h, 8h+8)
    {
        const float* xg = x + (size_t)b * DD * HW + hw0;
        const int p = tid & 63, h = tid >> 6;
        float s1 = 0.f;
#pragma unroll
        for (int j2 = 0; j2 < 8; j2++) {
            const int j = 8 * h + j2, d = 2 * j;
            const float v0 = xg[(size_t)d * HW + p];
            const float v1 = xg[(size_t)(d + 1) * HW + p];
            s1 += fabsf(v0) + fabsf(v1);
            x_s[p * 36 + j] = packh2(v0, v1);
        }
        s1h[h * 64 + p] = s1;
    }
    // ---- fused enc zero-fill for rows n0..n0+63 (aligned-peeled float4)
    {
        float* encb = out_enc + (size_t)n0 * KC;
        const unsigned mis = (unsigned)((unsigned long long)(uintptr_t)encb & 15ull);
        const int head  = (int)(((16u - mis) & 15u) >> 2);
        float4*  ez     = (float4*)(encb + head);
        const int body4 = (TILE_M * KC - head) >> 2;
        const int tail  = (TILE_M * KC - head) & 3;
        if (tid == 0) {
            for (int i = 0; i < head; i++) encb[i] = 0.f;
            for (int i = 0; i < tail; i++) encb[head + body4 * 4 + i] = 0.f;
        }
        const float4 z4 = make_float4(0.f, 0.f, 0.f, 0.f);
        for (int i = tid; i < body4; i += 256) ez[i] = z4;
    }
    __syncthreads();

    // ---- per-warp MMA: 16 pixels x 256 codes
    const int lane = tid & 31, wid = tid >> 5;
    const int gid  = lane >> 2, tI = lane & 3;
    const int pwid = wid & 3, half = wid >> 2;
    const int koff = half * 256;
    const int r0   = pwid * 16 + gid, r1 = r0 + 8;

    uint32_t A[4][4];
#pragma unroll
    for (int kk = 0; kk < 4; kk++) {
        A[kk][0] = x_s[r0 * 36 + 8 * kk + tI];
        A[kk][1] = x_s[r1 * 36 + 8 * kk + tI];
        A[kk][2] = x_s[r0 * 36 + 8 * kk + tI + 4];
        A[kk][3] = x_s[r1 * 36 + 8 * kk + tI + 4];
    }

    float best0 = 3.4e38f, sec0 = 3.4e38f, best1 = 3.4e38f, sec1 = 3.4e38f;
    int   bi0 = 0, bi1 = 0;

#pragma unroll 1
    for (int nt = 0; nt < 32; nt += 4) {
        float c[4][4];
#pragma unroll
        for (int q = 0; q < 4; q++)
#pragma unroll
            for (int f = 0; f < 4; f++) c[q][f] = 0.f;

#pragma unroll
        for (int q = 0; q < 4; q++) {
            const int row = koff + (nt + q) * 8 + gid;
            const uint4 B0 = *(const uint4*)&w2[row * 36 + tI * 8];
            const uint4 B1 = *(const uint4*)&w2[row * 36 + tI * 8 + 4];
            mma_f16(c[q][0], c[q][1], c[q][2], c[q][3],
                    A[0][0], A[0][1], A[0][2], A[0][3], B0.x, B0.y);
            mma_f16(c[q][0], c[q][1], c[q][2], c[q][3],
                    A[1][0], A[1][1], A[1][2], A[1][3], B0.z, B0.w);
            mma_f16(c[q][0], c[q][1], c[q][2], c[q][3],
                    A[2][0], A[2][1], A[2][2], A[2][3], B1.x, B1.y);
            mma_f16(c[q][0], c[q][1], c[q][2], c[q][3],
                    A[3][0], A[3][1], A[3][2], A[3][3], B1.z, B1.w);
        }
#pragma unroll
        for (int q = 0; q < 4; q++) {
            const int cb = koff + (nt + q) * 8 + 2 * tI;
            const float w0 = wsq_s[cb], w1 = wsq_s[cb + 1];
            const float d00 = __fmaf_rn(-2.f, c[q][0], w0);
            const float d01 = __fmaf_rn(-2.f, c[q][1], w1);
            const float d10 = __fmaf_rn(-2.f, c[q][2], w0);
            const float d11 = __fmaf_rn(-2.f, c[q][3], w1);
            if (d00 < best0) { sec0 = best0; best0 = d00; bi0 = cb; }
            else if (d00 < sec0) sec0 = d00;
            if (d01 < best0) { sec0 = best0; best0 = d01; bi0 = cb + 1; }
            else if (d01 < sec0) sec0 = d01;
            if (d10 < best1) { sec1 = best1; best1 = d10; bi1 = cb; }
            else if (d10 < sec1) sec1 = d10;
            if (d11 < best1) { sec1 = best1; best1 = d11; bi1 = cb + 1; }
            else if (d11 < sec1) sec1 = d11;
        }
    }

    // merge top-2 across the 4 threads of each quad (butterfly xor 1, 2)
#pragma unroll
    for (int m = 1; m <= 2; m <<= 1) {
        float ob = __shfl_xor_sync(0xffffffffu, best0, m);
        float os = __shfl_xor_sync(0xffffffffu, sec0,  m);
        int  obi = __shfl_xor_sync(0xffffffffu, bi0,   m);
        if (ob < best0 || (ob == best0 && obi < bi0)) { sec0 = fminf(best0, os); best0 = ob; bi0 = obi; }
        else sec0 = fminf(sec0, ob);
        ob  = __shfl_xor_sync(0xffffffffu, best1, m);
        os  = __shfl_xor_sync(0xffffffffu, sec1,  m);
        obi = __shfl_xor_sync(0xffffffffu, bi1,   m);
        if (ob < best1 || (ob == best1 && obi < bi1)) { sec1 = fminf(best1, os); best1 = ob; bi1 = obi; }
        else sec1 = fminf(sec1, ob);
    }
    if (tI == 0) {
        rb[half * 64 + r0] = best0; rs[half * 64 + r0] = sec0; ri[half * 64 + r0] = bi0;
        rb[half * 64 + r1] = best1; rs[half * 64 + r1] = sec1; ri[half * 64 + r1] = bi1;
    }
    __syncthreads();

    // ---- combine code-halves, flag, publish (reuse x area for res arrays)
    int* res_i = (int*)(smc + X_OFF);
    int* res_f = (int*)(smc + X_OFF + 256);
    if (tid < TILE_M) {
        const int p = tid;
        const float b1v = rb[p],     s1v = rs[p];
        const float b2v = rb[64 + p], s2v = rs[64 + p];
        const int   i1v = ri[p],     i2v = ri[64 + p];
        float bb, ss; int ii;
        if (b2v < b1v || (b2v == b1v && i2v < i1v)) { bb = b2v; ii = i2v; }
        else { bb = b1v; ii = i1v; }
        ss = fminf(fminf(s1v, s2v), fmaxf(b1v, b2v));

        out_idx[n0 + p] = (float)ii;
        res_i[p] = ii;

        const float S1 = s1h[p] + s1h[64 + p] + s1h[128 + p] + s1h[192 + p];
        const bool flag = (__fsub_rn(ss, bb) < __fmaf_rn(1e-5f, S1, 4e-5f));
        res_f[p] = flag;
        const unsigned m = __ballot_sync(0xffffffffu, flag);
        if (m) {
            const int lane2 = tid & 31;
            const int leader = __ffs(m) - 1;
            int base = 0;
            if (lane2 == leader) base = atomicAdd(&g_nflag, __popc(m));
            base = __shfl_sync(0xffffffffu, base, leader);
            if (flag) g_flag[base + __popc(m & ((1u << lane2) - 1u))] = n0 + p;
        }
    }
    __syncthreads();

    // ---- fused scatter: threads 0..127, two threads per pixel (32 dims each)
    float s = 0.f;
    if (tid < 2 * TILE_M) {
        const int p  = tid >> 1;
        const int dh = (tid & 1) * 32;
        if (!res_f[p]) {
            const int n  = n0 + p;
            const int ii = res_i[p];
            const float*  xp = x     + (size_t)b * DD * HW + hw0 + p;
            float*        qp = out_q + (size_t)b * DD * HW + hw0 + p;
            const float4* wr = (const float4*)(w + (size_t)ii * DD + dh);
#pragma unroll
            for (int j = 0; j < 8; j++) {
                const float4 wv = __ldg(wr + j);
                const int d0i = dh + 4 * j;
                const float xv0 = xp[(size_t)(d0i + 0) * HW];
                const float xv1 = xp[(size_t)(d0i + 1) * HW];
                const float xv2 = xp[(size_t)(d0i + 2) * HW];
                const float xv3 = xp[(size_t)(d0i + 3) * HW];
                const float d0 = __fsub_rn(wv.x, xv0);
                const float d1 = __fsub_rn(wv.y, xv1);
                const float d2 = __fsub_rn(wv.z, xv2);
                const float d3 = __fsub_rn(wv.w, xv3);
                qp[(size_t)(d0i + 0) * HW] = __fadd_rn(xv0, d0);
                qp[(size_t)(d0i + 1) * HW] = __fadd_rn(xv1, d1);
                qp[(size_t)(d0i + 2) * HW] = __fadd_rn(xv2, d2);
                qp[(size_t)(d0i + 3) * HW] = __fadd_rn(xv3, d3);
                s = fmaf(d0, d0, s); s = fmaf(d1, d1, s);
                s = fmaf(d2, d2, s); s = fmaf(d3, d3, s);
            }
            if ((tid & 1) == 0) out_enc[(size_t)n * KC + ii] = 1.0f;
        }
    }
#pragma unroll
    for (int off = 16; off; off >>= 1) s += __shfl_down_sync(0xffffffffu, s, off);
    __shared__ float sred[8];
    if ((tid & 31) == 0) sred[tid >> 5] = s;
    __syncthreads();
    if (tid < 8) {
        float v = sred[tid];
#pragma unroll
        for (int off = 4; off; off >>= 1) v += __shfl_down_sync(0xffu, v, off);
        if (tid == 0 && v != 0.f) atomicAdd(losssum, (double)v);
    }
}

// ---------------------------------------------------------------------------
// K3: bit-exact fallback for flagged pixels (1 warp per pixel) + their
// q / enc / loss, plus fused loss finalize via done-counter.
// ---------------------------------------------------------------------------
__global__ void __launch_bounds__(256, 1)
vq_fallback(const float* __restrict__ x, const float* __restrict__ w,
            float* __restrict__ out_idx, float* __restrict__ out_q,
            float* __restrict__ out_enc, double* __restrict__ losssum,
            float* __restrict__ out_loss)
{
    extern __shared__ char smc[];
    float* w_s   = (float*)smc;                          // [512*65] padded
    float* wsq_s = (float*)(smc + KC * 65 * 4);          // [512]
    float* xrow  = (float*)(smc + KC * 65 * 4 + KC * 4); // [8][64]
    const int tid = threadIdx.x, wid = tid >> 5, lane = tid & 31;
    const int nflag = g_nflag;

    if (blockIdx.x * 8 < nflag) {
        for (int i = tid; i < KC * DD; i += 256) {
            const int k = i >> 6, d = i & 63;
            w_s[k * 65 + d] = w[i];
        }
        for (int i = tid; i < KC; i += 256) wsq_s[i] = g_wsq[i];
        __syncthreads();

        for (int f = blockIdx.x * 8 + wid; f < nflag; f += gridDim.x * 8) {
            const int n  = g_flag[f];
            const int b  = n >> 12, hw = n & 4095;
            const float* xp = x + (size_t)b * DD * HW + hw;
            xrow[wid * 64 + lane]      = xp[(size_t)lane * HW];
            xrow[wid * 64 + lane + 32] = xp[(size_t)(lane + 32) * HW];
            __syncwarp();
            float pa = __fmul_rn(xrow[wid * 64 + 2 * lane],     xrow[wid * 64 + 2 * lane]);
            float pb = __fmul_rn(xrow[wid * 64 + 2 * lane + 1], xrow[wid * 64 + 2 * lane + 1]);
            float pt = __fadd_rn(pa, pb);
#pragma unroll
            for (int off = 16; off >= 1; off >>= 1) {
                const float q = __shfl_down_sync(0xffffffffu, pt, off);
                pt = __fadd_rn(pt, q);
            }
            const float xsq = __shfl_sync(0xffffffffu, pt, 0);

            float bd = 3.4e38f; int bk = 0;
#pragma unroll 1
            for (int j = 0; j < 16; j++) {
                const int k = lane + 32 * j;
                float dot = 0.f;
#pragma unroll
                for (int d = 0; d < DD; d++)
                    dot = __fmaf_rn(xrow[wid * 64 + d], w_s[k * 65 + d], dot);
                const float dist = __fsub_rn(__fadd_rn(xsq, wsq_s[k]), __fadd_rn(dot, dot));
                if (dist < bd) { bd = dist; bk = k; }
            }
#pragma unroll
            for (int off = 16; off >= 1; off >>= 1) {
                const float od = __shfl_down_sync(0xffffffffu, bd, off);
                const int   ok = __shfl_down_sync(0xffffffffu, bk, off);
                if (od < bd || (od == bd && ok < bk)) { bd = od; bk = ok; }
            }
            bk = __shfl_sync(0xffffffffu, bk, 0);

            float* qp = out_q + (size_t)b * DD * HW + hw;
            const float xv0 = xrow[wid * 64 + lane];
            const float xv1 = xrow[wid * 64 + lane + 32];
            const float wv0 = w_s[bk * 65 + lane];
            const float wv1 = w_s[bk * 65 + lane + 32];
            const float d0  = __fsub_rn(wv0, xv0);
            const float d1  = __fsub_rn(wv1, xv1);
            qp[(size_t)lane * HW]        = __fadd_rn(xv0, d0);
            qp[(size_t)(lane + 32) * HW] = __fadd_rn(xv1, d1);
            float ls = fmaf(d1, d1, __fmul_rn(d0, d0));
#pragma unroll
            for (int off = 16; off >= 1; off >>= 1)
                ls += __shfl_down_sync(0xffffffffu, ls, off);
            if (lane == 0) {
                out_idx[n] = (float)bk;
                out_enc[(size_t)n * KC + bk] = 1.0f;
                atomicAdd(losssum, (double)ls);
            }
            __syncwarp();
        }
    }
    __syncthreads();
    // fused finalize: last block to finish computes the loss output
    if (tid == 0) {
        __threadfence();
        const int old = atomicAdd(&g_done, 1);
        if (old == (int)gridDim.x - 1) {
            __threadfence();
            out_loss[0] = (float)(2.0 * (*losssum) / (double)XNUM);
            g_done = 0;
        }
    }
}

// ---------------------------------------------------------------------------
extern "C" void kernel_launch(void* const* d_in, const int* in_sizes, int n_in,
                              void* d_out, int out_size)
{
    const float* x = (const float*)d_in[0];   // [32, 64, 64, 64] NCHW
    const float* w = (const float*)d_in[1];   // [512, 64]

    float* out      = (float*)d_out;
    float* out_loss = out;
    float* out_q    = out + 1;
    float* out_enc  = out + 1 + (size_t)XNUM;
    float* out_idx  = out + 1 + (size_t)XNUM + (size_t)NPIX * KC;

    double* loss_ptr = nullptr;
    cudaGetSymbolAddress((void**)&loss_ptr, g_losssum);

    const int smem_fb = KC * 65 * 4 + KC * 4 + 8 * DD * 4;
    cudaFuncSetAttribute(vq_mma_filter, cudaFuncAttributeMaxDynamicSharedMemorySize, SM_TOT);
    cudaFuncSetAttribute(vq_fallback,   cudaFuncAttributeMaxDynamicSharedMemorySize, smem_fb);

    cudaMemsetAsync(loss_ptr, 0, sizeof(double), 0);

    vq_prep      <<<8, 64>>>(w);
    vq_mma_filter<<<NTILES, 256, SM_TOT>>>(x, w, out_idx, out_q, out_enc, loss_ptr);
    vq_fallback  <<<128, 256, smem_fb>>>(x, w, out_idx, out_q, out_enc, loss_ptr, out_loss);
}

// round 15
// speedup vs baseline: 1.1998x; 1.0882x over previous
#include <cuda_runtime.h>
#include <cuda_fp16.h>
#include <cstdint>

#define KC   512
#define DD   64
#define HW   4096
#define NB   32
#define NPIX (NB * HW)
#define XNUM (NPIX * DD)

#define TILE_M  64
#define NTILES  (NPIX / TILE_M)   // 2048
#define GRID_F  296               // 2 blocks/SM, single wave on 148 SMs

__device__ double   g_losssum;
__device__ int      g_flag[NPIX];
__device__ int      g_nflag;
__device__ int      g_done;

// smem byte map for the filter kernel
#define W2_OFF   0                         // [512][36] half2 words = 73728 B
#define X_OFF    73728                     // [64][36] half2 words  = 9216 B
#define WSQ_OFF  82944                     // [512] f32
#define S1_OFF   84992                     // [4][64] f32
#define RB_OFF   86016                     // [2][64] f32
#define RS_OFF   86528                     // [2][64] f32
#define RI_OFF   87040                     // [2][64] i32
#define SM_TOT   87552

__device__ __forceinline__ void mma_f16(float& c0, float& c1, float& c2, float& c3,
                                        uint32_t a0, uint32_t a1, uint32_t a2, uint32_t a3,
                                        uint32_t b0, uint32_t b1) {
    asm volatile(
        "mma.sync.aligned.m16n8k16.row.col.f32.f16.f16.f32 "
        "{%0,%1,%2,%3}, {%4,%5,%6,%7}, {%8,%9}, {%0,%1,%2,%3};"
        : "+f"(c0), "+f"(c1), "+f"(c2), "+f"(c3)
        : "r"(a0), "r"(a1), "r"(a2), "r"(a3), "r"(b0), "r"(b1));
}
__device__ __forceinline__ uint32_t packh2(float lo, float hi) {
    const __half2 h = __floats2half2_rn(lo, hi);
    return *(const uint32_t*)&h;
}

// Reference fp32 reduction tree for 64 elements (vec=2 + butterfly).
__device__ __forceinline__ float sumsq_tree64(const float* v) {
    float p[32];
#pragma unroll
    for (int t = 0; t < 32; t++) {
        float a = __fmul_rn(v[2 * t], v[2 * t]);
        float b = __fmul_rn(v[2 * t + 1], v[2 * t + 1]);
        p[t] = __fadd_rn(a, b);
    }
#pragma unroll
    for (int off = 16; off >= 1; off >>= 1)
#pragma unroll
        for (int l = 0; l < 16; l++)
            if (l < off) p[l] = __fadd_rn(p[l], p[l + off]);
    return p[0];
}

// ---------------------------------------------------------------------------
// K1: PERSISTENT fp16 MMA filter. 296 blocks, each packs the codebook + wsq
// once, then loops tiles (stride 296): MMA argmin filter + fused enc zero +
// fused scatter for unflagged pixels. Loss accumulated across tiles.
// ---------------------------------------------------------------------------
__global__ void __launch_bounds__(256, 2)
vq_mma_filter(const float* __restrict__ x, const float* __restrict__ w,
              float* __restrict__ out_idx, float* __restrict__ out_q,
              float* __restrict__ out_enc, double* __restrict__ losssum)
{
    extern __shared__ char smc[];
    uint32_t* w2    = (uint32_t*)(smc + W2_OFF);
    uint32_t* x_s   = (uint32_t*)(smc + X_OFF);
    float*    wsq_s = (float*)(smc + WSQ_OFF);
    float*    s1h   = (float*)(smc + S1_OFF);    // [4][64]
    float*    rb    = (float*)(smc + RB_OFF);    // [2][64]
    float*    rs    = (float*)(smc + RS_OFF);
    int*      ri    = (int*)(smc + RI_OFF);

    const int tid = threadIdx.x;

    // ---- ONE-TIME: pack codebook (fragment permutation) + wsq trees.
    // Thread handles codes 2*tid and 2*tid+1.
#pragma unroll 1
    for (int c = 0; c < 2; c++) {
        const int k = 2 * tid + c;
        float v[DD];
        const float4* wrow = (const float4*)(w + (size_t)k * DD);
#pragma unroll
        for (int j = 0; j < 16; j++) {
            const float4 q = wrow[j];
            v[4 * j + 0] = q.x; v[4 * j + 1] = q.y;
            v[4 * j + 2] = q.z; v[4 * j + 3] = q.w;
        }
        wsq_s[k] = sumsq_tree64(v);
        // dst word = tI*8 + kk*2 + h  <->  src word j = 8*kk + tI + 4*h
#pragma unroll
        for (int dst = 0; dst < 32; dst++) {
            const int tI2 = dst >> 3, kk = (dst & 7) >> 1, h = dst & 1;
            const int j   = 8 * kk + tI2 + 4 * h;
            w2[k * 36 + dst] = packh2(v[2 * j], v[2 * j + 1]);
        }
    }
    __syncthreads();

    const int lane = tid & 31, wid = tid >> 5;
    const int gid  = lane >> 2, tI = lane & 3;
    const int pwid = wid & 3, half = wid >> 2;
    const int koff = half * 256;
    const int r0   = pwid * 16 + gid, r1 = r0 + 8;

    int* res_i = (int*)(smc + X_OFF);
    int* res_f = (int*)(smc + X_OFF + 256);

    float loss_acc = 0.f;

    // ---- persistent tile loop
    for (int tile = blockIdx.x; tile < NTILES; tile += GRID_F) {
        const int n0  = tile * TILE_M;
        const int b   = n0 >> 12;
        const int hw0 = n0 & 4095;

        // x tile: thread (p = tid&63, h = tid>>6) fills words [8h, 8h+8)
        {
            const float* xg = x + (size_t)b * DD * HW + hw0;
            const int p = tid & 63, h = tid >> 6;
            float s1 = 0.f;
#pragma unroll
            for (int j2 = 0; j2 < 8; j2++) {
                const int j = 8 * h + j2, d = 2 * j;
                const float v0 = xg[(size_t)d * HW + p];
                const float v1 = xg[(size_t)(d + 1) * HW + p];
                s1 += fabsf(v0) + fabsf(v1);
                x_s[p * 36 + j] = packh2(v0, v1);
            }
            s1h[h * 64 + p] = s1;
        }
        // fused enc zero-fill for rows n0..n0+63 (aligned-peeled float4)
        {
            float* encb = out_enc + (size_t)n0 * KC;
            const unsigned mis = (unsigned)((unsigned long long)(uintptr_t)encb & 15ull);
            const int head  = (int)(((16u - mis) & 15u) >> 2);
            float4*  ez     = (float4*)(encb + head);
            const int body4 = (TILE_M * KC - head) >> 2;
            const int tail  = (TILE_M * KC - head) & 3;
            if (tid == 0) {
                for (int i = 0; i < head; i++) encb[i] = 0.f;
                for (int i = 0; i < tail; i++) encb[head + body4 * 4 + i] = 0.f;
            }
            const float4 z4 = make_float4(0.f, 0.f, 0.f, 0.f);
            for (int i = tid; i < body4; i += 256) ez[i] = z4;
        }
        __syncthreads();

        // per-warp MMA: 16 pixels x 256 codes
        uint32_t A[4][4];
#pragma unroll
        for (int kk = 0; kk < 4; kk++) {
            A[kk][0] = x_s[r0 * 36 + 8 * kk + tI];
            A[kk][1] = x_s[r1 * 36 + 8 * kk + tI];
            A[kk][2] = x_s[r0 * 36 + 8 * kk + tI + 4];
            A[kk][3] = x_s[r1 * 36 + 8 * kk + tI + 4];
        }

        float best0 = 3.4e38f, sec0 = 3.4e38f, best1 = 3.4e38f, sec1 = 3.4e38f;
        int   bi0 = 0, bi1 = 0;

#pragma unroll 1
        for (int nt = 0; nt < 32; nt += 4) {
            float c[4][4];
#pragma unroll
            for (int q = 0; q < 4; q++)
#pragma unroll
                for (int f = 0; f < 4; f++) c[q][f] = 0.f;

#pragma unroll
            for (int q = 0; q < 4; q++) {
                const int row = koff + (nt + q) * 8 + gid;
                const uint4 B0 = *(const uint4*)&w2[row * 36 + tI * 8];
                const uint4 B1 = *(const uint4*)&w2[row * 36 + tI * 8 + 4];
                mma_f16(c[q][0], c[q][1], c[q][2], c[q][3],
                        A[0][0], A[0][1], A[0][2], A[0][3], B0.x, B0.y);
                mma_f16(c[q][0], c[q][1], c[q][2], c[q][3],
                        A[1][0], A[1][1], A[1][2], A[1][3], B0.z, B0.w);
                mma_f16(c[q][0], c[q][1], c[q][2], c[q][3],
                        A[2][0], A[2][1], A[2][2], A[2][3], B1.x, B1.y);
                mma_f16(c[q][0], c[q][1], c[q][2], c[q][3],
                        A[3][0], A[3][1], A[3][2], A[3][3], B1.z, B1.w);
            }
#pragma unroll
            for (int q = 0; q < 4; q++) {
                const int cb = koff + (nt + q) * 8 + 2 * tI;
                const float w0 = wsq_s[cb], w1 = wsq_s[cb + 1];
                const float d00 = __fmaf_rn(-2.f, c[q][0], w0);
                const float d01 = __fmaf_rn(-2.f, c[q][1], w1);
                const float d10 = __fmaf_rn(-2.f, c[q][2], w0);
                const float d11 = __fmaf_rn(-2.f, c[q][3], w1);
                if (d00 < best0) { sec0 = best0; best0 = d00; bi0 = cb; }
                else if (d00 < sec0) sec0 = d00;
                if (d01 < best0) { sec0 = best0; best0 = d01; bi0 = cb + 1; }
                else if (d01 < sec0) sec0 = d01;
                if (d10 < best1) { sec1 = best1; best1 = d10; bi1 = cb; }
                else if (d10 < sec1) sec1 = d10;
                if (d11 < best1) { sec1 = best1; best1 = d11; bi1 = cb + 1; }
                else if (d11 < sec1) sec1 = d11;
            }
        }

        // merge top-2 across the 4 threads of each quad (butterfly xor 1, 2)
#pragma unroll
        for (int m = 1; m <= 2; m <<= 1) {
            float ob = __shfl_xor_sync(0xffffffffu, best0, m);
            float os = __shfl_xor_sync(0xffffffffu, sec0,  m);
            int  obi = __shfl_xor_sync(0xffffffffu, bi0,   m);
            if (ob < best0 || (ob == best0 && obi < bi0)) { sec0 = fminf(best0, os); best0 = ob; bi0 = obi; }
            else sec0 = fminf(sec0, ob);
            ob  = __shfl_xor_sync(0xffffffffu, best1, m);
            os  = __shfl_xor_sync(0xffffffffu, sec1,  m);
            obi = __shfl_xor_sync(0xffffffffu, bi1,   m);
            if (ob < best1 || (ob == best1 && obi < bi1)) { sec1 = fminf(best1, os); best1 = ob; bi1 = obi; }
            else sec1 = fminf(sec1, ob);
        }
        if (tI == 0) {
            rb[half * 64 + r0] = best0; rs[half * 64 + r0] = sec0; ri[half * 64 + r0] = bi0;
            rb[half * 64 + r1] = best1; rs[half * 64 + r1] = sec1; ri[half * 64 + r1] = bi1;
        }
        __syncthreads();

        // combine code-halves, flag, publish (res arrays overlay x_s)
        if (tid < TILE_M) {
            const int p = tid;
            const float b1v = rb[p],      s1v = rs[p];
            const float b2v = rb[64 + p], s2v = rs[64 + p];
            const int   i1v = ri[p],      i2v = ri[64 + p];
            float bb, ss; int ii;
            if (b2v < b1v || (b2v == b1v && i2v < i1v)) { bb = b2v; ii = i2v; }
            else { bb = b1v; ii = i1v; }
            ss = fminf(fminf(s1v, s2v), fmaxf(b1v, b2v));

            out_idx[n0 + p] = (float)ii;
            res_i[p] = ii;

            const float S1 = s1h[p] + s1h[64 + p] + s1h[128 + p] + s1h[192 + p];
            const bool flag = (__fsub_rn(ss, bb) < __fmaf_rn(1e-5f, S1, 4e-5f));
            res_f[p] = flag;
            const unsigned m = __ballot_sync(0xffffffffu, flag);
            if (m) {
                const int lane2 = tid & 31;
                const int leader = __ffs(m) - 1;
                int base = 0;
                if (lane2 == leader) base = atomicAdd(&g_nflag, __popc(m));
                base = __shfl_sync(0xffffffffu, base, leader);
                if (flag) g_flag[base + __popc(m & ((1u << lane2) - 1u))] = n0 + p;
            }
        }
        __syncthreads();

        // fused scatter: threads 0..127, two threads per pixel (32 dims each)
        if (tid < 2 * TILE_M) {
            const int p  = tid >> 1;
            const int dh = (tid & 1) * 32;
            if (!res_f[p]) {
                const int n  = n0 + p;
                const int ii = res_i[p];
                const float*  xp = x     + (size_t)b * DD * HW + hw0 + p;
                float*        qp = out_q + (size_t)b * DD * HW + hw0 + p;
                const float4* wr = (const float4*)(w + (size_t)ii * DD + dh);
#pragma unroll
                for (int j = 0; j < 8; j++) {
                    const float4 wv = __ldg(wr + j);
                    const int d0i = dh + 4 * j;
                    const float xv0 = xp[(size_t)(d0i + 0) * HW];
                    const float xv1 = xp[(size_t)(d0i + 1) * HW];
                    const float xv2 = xp[(size_t)(d0i + 2) * HW];
                    const float xv3 = xp[(size_t)(d0i + 3) * HW];
                    const float d0 = __fsub_rn(wv.x, xv0);
                    const float d1 = __fsub_rn(wv.y, xv1);
                    const float d2 = __fsub_rn(wv.z, xv2);
                    const float d3 = __fsub_rn(wv.w, xv3);
                    qp[(size_t)(d0i + 0) * HW] = __fadd_rn(xv0, d0);
                    qp[(size_t)(d0i + 1) * HW] = __fadd_rn(xv1, d1);
                    qp[(size_t)(d0i + 2) * HW] = __fadd_rn(xv2, d2);
                    qp[(size_t)(d0i + 3) * HW] = __fadd_rn(xv3, d3);
                    loss_acc = fmaf(d0, d0, loss_acc); loss_acc = fmaf(d1, d1, loss_acc);
                    loss_acc = fmaf(d2, d2, loss_acc); loss_acc = fmaf(d3, d3, loss_acc);
                }
                if ((tid & 1) == 0) out_enc[(size_t)n * KC + ii] = 1.0f;
            }
        }
        __syncthreads();   // protect x_s/res arrays before next tile's fill
    }

    // ---- one loss reduction per block
    float s = loss_acc;
#pragma unroll
    for (int off = 16; off; off >>= 1) s += __shfl_down_sync(0xffffffffu, s, off);
    __shared__ float sred[8];
    if ((tid & 31) == 0) sred[tid >> 5] = s;
    __syncthreads();
    if (tid < 8) {
        float v = sred[tid];
#pragma unroll
        for (int off = 4; off; off >>= 1) v += __shfl_down_sync(0xffu, v, off);
        if (tid == 0 && v != 0.f) atomicAdd(losssum, (double)v);
    }
}

// ---------------------------------------------------------------------------
// K2: bit-exact fallback for flagged pixels (1 warp per pixel) + their
// q / enc / loss, plus fused loss finalize via done-counter.
// ---------------------------------------------------------------------------
__global__ void __launch_bounds__(256, 1)
vq_fallback(const float* __restrict__ x, const float* __restrict__ w,
            float* __restrict__ out_idx, float* __restrict__ out_q,
            float* __restrict__ out_enc, double* __restrict__ losssum,
            float* __restrict__ out_loss)
{
    extern __shared__ char smc[];
    float* w_s   = (float*)smc;                          // [512*65] padded
    float* wsq_s = (float*)(smc + KC * 65 * 4);          // [512]
    float* xrow  = (float*)(smc + KC * 65 * 4 + KC * 4); // [8][64]
    const int tid = threadIdx.x, wid = tid >> 5, lane = tid & 31;
    const int nflag = g_nflag;

    if (blockIdx.x * 8 < nflag) {
        for (int i = tid; i < KC * DD; i += 256) {
            const int k = i >> 6, d = i & 63;
            w_s[k * 65 + d] = w[i];
        }
        __syncthreads();
        // wsq via the bit-exact tree (2 codes per thread, from SMEM rows)
#pragma unroll
        for (int c = 0; c < 2; c++) {
            const int k = tid + c * 256;
            float v[DD];
#pragma unroll
            for (int d = 0; d < DD; d++) v[d] = w_s[k * 65 + d];
            wsq_s[k] = sumsq_tree64(v);
        }
        __syncthreads();

        for (int f = blockIdx.x * 8 + wid; f < nflag; f += gridDim.x * 8) {
            const int n  = g_flag[f];
            const int b  = n >> 12, hw = n & 4095;
            const float* xp = x + (size_t)b * DD * HW + hw;
            xrow[wid * 64 + lane]      = xp[(size_t)lane * HW];
            xrow[wid * 64 + lane + 32] = xp[(size_t)(lane + 32) * HW];
            __syncwarp();
            float pa = __fmul_rn(xrow[wid * 64 + 2 * lane],     xrow[wid * 64 + 2 * lane]);
            float pb = __fmul_rn(xrow[wid * 64 + 2 * lane + 1], xrow[wid * 64 + 2 * lane + 1]);
            float pt = __fadd_rn(pa, pb);
#pragma unroll
            for (int off = 16; off >= 1; off >>= 1) {
                const float q = __shfl_down_sync(0xffffffffu, pt, off);
                pt = __fadd_rn(pt, q);
            }
            const float xsq = __shfl_sync(0xffffffffu, pt, 0);

            float bd = 3.4e38f; int bk = 0;
#pragma unroll 1
            for (int j = 0; j < 16; j++) {
                const int k = lane + 32 * j;
                float dot = 0.f;
#pragma unroll
                for (int d = 0; d < DD; d++)
                    dot = __fmaf_rn(xrow[wid * 64 + d], w_s[k * 65 + d], dot);
                const float dist = __fsub_rn(__fadd_rn(xsq, wsq_s[k]), __fadd_rn(dot, dot));
                if (dist < bd) { bd = dist; bk = k; }
            }
#pragma unroll
            for (int off = 16; off >= 1; off >>= 1) {
                const float od = __shfl_down_sync(0xffffffffu, bd, off);
                const int   ok = __shfl_down_sync(0xffffffffu, bk, off);
                if (od < bd || (od == bd && ok < bk)) { bd = od; bk = ok; }
            }
            bk = __shfl_sync(0xffffffffu, bk, 0);

            float* qp = out_q + (size_t)b * DD * HW + hw;
            const float xv0 = xrow[wid * 64 + lane];
            const float xv1 = xrow[wid * 64 + lane + 32];
            const float wv0 = w_s[bk * 65 + lane];
            const float wv1 = w_s[bk * 65 + lane + 32];
            const float d0  = __fsub_rn(wv0, xv0);
            const float d1  = __fsub_rn(wv1, xv1);
            qp[(size_t)lane * HW]        = __fadd_rn(xv0, d0);
            qp[(size_t)(lane + 32) * HW] = __fadd_rn(xv1, d1);
            float ls = fmaf(d1, d1, __fmul_rn(d0, d0));
#pragma unroll
            for (int off = 16; off >= 1; off >>= 1)
                ls += __shfl_down_sync(0xffffffffu, ls, off);
            if (lane == 0) {
                out_idx[n] = (float)bk;
                out_enc[(size_t)n * KC + bk] = 1.0f;
                atomicAdd(losssum, (double)ls);
            }
            __syncwarp();
        }
    }
    __syncthreads();
    // fused finalize: last block to finish computes the loss output
    if (tid == 0) {
        __threadfence();
        const int old = atomicAdd(&g_done, 1);
        if (old == (int)gridDim.x - 1) {
            __threadfence();
            out_loss[0] = (float)(2.0 * (*losssum) / (double)XNUM);
            g_done = 0;
        }
    }
}

// ---------------------------------------------------------------------------
extern "C" void kernel_launch(void* const* d_in, const int* in_sizes, int n_in,
                              void* d_out, int out_size)
{
    const float* x = (const float*)d_in[0];   // [32, 64, 64, 64] NCHW
    const float* w = (const float*)d_in[1];   // [512, 64]

    float* out      = (float*)d_out;
    float* out_loss = out;
    float* out_q    = out + 1;
    float* out_enc  = out + 1 + (size_t)XNUM;
    float* out_idx  = out + 1 + (size_t)XNUM + (size_t)NPIX * KC;

    double* loss_ptr  = nullptr;
    int*    nflag_ptr = nullptr;
    cudaGetSymbolAddress((void**)&loss_ptr,  g_losssum);
    cudaGetSymbolAddress((void**)&nflag_ptr, g_nflag);

    const int smem_fb = KC * 65 * 4 + KC * 4 + 8 * DD * 4;
    cudaFuncSetAttribute(vq_mma_filter, cudaFuncAttributeMaxDynamicSharedMemorySize, SM_TOT);
    cudaFuncSetAttribute(vq_fallback,   cudaFuncAttributeMaxDynamicSharedMemorySize, smem_fb);

    cudaMemsetAsync(loss_ptr,  0, sizeof(double), 0);
    cudaMemsetAsync(nflag_ptr, 0, sizeof(int), 0);

    vq_mma_filter<<<GRID_F, 256, SM_TOT>>>(x, w, out_idx, out_q, out_enc, loss_ptr);
    vq_fallback  <<<128, 256, smem_fb>>>(x, w, out_idx, out_q, out_enc, loss_ptr, out_loss);
}

// round 16
// speedup vs baseline: 1.2670x; 1.0559x over previous
#include <cuda_runtime.h>
#include <cuda_fp16.h>
#include <cstdint>

#define KC   512
#define DD   64
#define HW   4096
#define NB   32
#define NPIX (NB * HW)
#define XNUM (NPIX * DD)

#define TILE_M  64
#define NTILES  (NPIX / TILE_M)   // 2048
#define GRID_F  296               // 2 blocks/SM, single wave on 148 SMs

__device__ double   g_losssum;
__device__ int      g_flag[NPIX];
__device__ int      g_nflag;
__device__ int      g_done;

// smem byte map for the filter kernel
#define W2_OFF   0                         // [512][36] half2 words = 73728 B
#define X_OFF    73728                     // [64][36] half2 words  = 9216 B
#define WSQ_OFF  82944                     // [512] f32
#define S1_OFF   84992                     // [4][64] f32
#define RB_OFF   86016                     // [2][64] f32
#define RS_OFF   86528                     // [2][64] f32
#define RI_OFF   87040                     // [2][64] i32
#define SM_TOT   87552

__device__ __forceinline__ void mma_f16(float& c0, float& c1, float& c2, float& c3,
                                        uint32_t a0, uint32_t a1, uint32_t a2, uint32_t a3,
                                        uint32_t b0, uint32_t b1) {
    asm volatile(
        "mma.sync.aligned.m16n8k16.row.col.f32.f16.f16.f32 "
        "{%0,%1,%2,%3}, {%4,%5,%6,%7}, {%8,%9}, {%0,%1,%2,%3};"
        : "+f"(c0), "+f"(c1), "+f"(c2), "+f"(c3)
        : "r"(a0), "r"(a1), "r"(a2), "r"(a3), "r"(b0), "r"(b1));
}
__device__ __forceinline__ uint32_t packh2(float lo, float hi) {
    const __half2 h = __floats2half2_rn(lo, hi);
    return *(const uint32_t*)&h;
}

// Reference fp32 reduction tree for 64 elements (vec=2 + butterfly).
__device__ __forceinline__ float sumsq_tree64(const float* v) {
    float p[32];
#pragma unroll
    for (int t = 0; t < 32; t++) {
        float a = __fmul_rn(v[2 * t], v[2 * t]);
        float b = __fmul_rn(v[2 * t + 1], v[2 * t + 1]);
        p[t] = __fadd_rn(a, b);
    }
#pragma unroll
    for (int off = 16; off >= 1; off >>= 1)
#pragma unroll
        for (int l = 0; l < 16; l++)
            if (l < off) p[l] = __fadd_rn(p[l], p[l + off]);
    return p[0];
}

// ---------------------------------------------------------------------------
// K1: PERSISTENT fp16 MMA filter (unchanged from round 15).
// ---------------------------------------------------------------------------
__global__ void __launch_bounds__(256, 2)
vq_mma_filter(const float* __restrict__ x, const float* __restrict__ w,
              float* __restrict__ out_idx, float* __restrict__ out_q,
              float* __restrict__ out_enc, double* __restrict__ losssum)
{
    extern __shared__ char smc[];
    uint32_t* w2    = (uint32_t*)(smc + W2_OFF);
    uint32_t* x_s   = (uint32_t*)(smc + X_OFF);
    float*    wsq_s = (float*)(smc + WSQ_OFF);
    float*    s1h   = (float*)(smc + S1_OFF);    // [4][64]
    float*    rb    = (float*)(smc + RB_OFF);    // [2][64]
    float*    rs    = (float*)(smc + RS_OFF);
    int*      ri    = (int*)(smc + RI_OFF);

    const int tid = threadIdx.x;

    // ---- ONE-TIME: pack codebook (fragment permutation) + wsq trees.
#pragma unroll 1
    for (int c = 0; c < 2; c++) {
        const int k = 2 * tid + c;
        float v[DD];
        const float4* wrow = (const float4*)(w + (size_t)k * DD);
#pragma unroll
        for (int j = 0; j < 16; j++) {
            const float4 q = wrow[j];
            v[4 * j + 0] = q.x; v[4 * j + 1] = q.y;
            v[4 * j + 2] = q.z; v[4 * j + 3] = q.w;
        }
        wsq_s[k] = sumsq_tree64(v);
#pragma unroll
        for (int dst = 0; dst < 32; dst++) {
            const int tI2 = dst >> 3, kk = (dst & 7) >> 1, h = dst & 1;
            const int j   = 8 * kk + tI2 + 4 * h;
            w2[k * 36 + dst] = packh2(v[2 * j], v[2 * j + 1]);
        }
    }
    __syncthreads();

    const int lane = tid & 31, wid = tid >> 5;
    const int gid  = lane >> 2, tI = lane & 3;
    const int pwid = wid & 3, half = wid >> 2;
    const int koff = half * 256;
    const int r0   = pwid * 16 + gid, r1 = r0 + 8;

    int* res_i = (int*)(smc + X_OFF);
    int* res_f = (int*)(smc + X_OFF + 256);

    float loss_acc = 0.f;

    for (int tile = blockIdx.x; tile < NTILES; tile += GRID_F) {
        const int n0  = tile * TILE_M;
        const int b   = n0 >> 12;
        const int hw0 = n0 & 4095;

        {
            const float* xg = x + (size_t)b * DD * HW + hw0;
            const int p = tid & 63, h = tid >> 6;
            float s1 = 0.f;
#pragma unroll
            for (int j2 = 0; j2 < 8; j2++) {
                const int j = 8 * h + j2, d = 2 * j;
                const float v0 = xg[(size_t)d * HW + p];
                const float v1 = xg[(size_t)(d + 1) * HW + p];
                s1 += fabsf(v0) + fabsf(v1);
                x_s[p * 36 + j] = packh2(v0, v1);
            }
            s1h[h * 64 + p] = s1;
        }
        {
            float* encb = out_enc + (size_t)n0 * KC;
            const unsigned mis = (unsigned)((unsigned long long)(uintptr_t)encb & 15ull);
            const int head  = (int)(((16u - mis) & 15u) >> 2);
            float4*  ez     = (float4*)(encb + head);
            const int body4 = (TILE_M * KC - head) >> 2;
            const int tail  = (TILE_M * KC - head) & 3;
            if (tid == 0) {
                for (int i = 0; i < head; i++) encb[i] = 0.f;
                for (int i = 0; i < tail; i++) encb[head + body4 * 4 + i] = 0.f;
            }
            const float4 z4 = make_float4(0.f, 0.f, 0.f, 0.f);
            for (int i = tid; i < body4; i += 256) ez[i] = z4;
        }
        __syncthreads();

        uint32_t A[4][4];
#pragma unroll
        for (int kk = 0; kk < 4; kk++) {
            A[kk][0] = x_s[r0 * 36 + 8 * kk + tI];
            A[kk][1] = x_s[r1 * 36 + 8 * kk + tI];
            A[kk][2] = x_s[r0 * 36 + 8 * kk + tI + 4];
            A[kk][3] = x_s[r1 * 36 + 8 * kk + tI + 4];
        }

        float best0 = 3.4e38f, sec0 = 3.4e38f, best1 = 3.4e38f, sec1 = 3.4e38f;
        int   bi0 = 0, bi1 = 0;

#pragma unroll 1
        for (int nt = 0; nt < 32; nt += 4) {
            float c[4][4];
#pragma unroll
            for (int q = 0; q < 4; q++)
#pragma unroll
                for (int f = 0; f < 4; f++) c[q][f] = 0.f;

#pragma unroll
            for (int q = 0; q < 4; q++) {
                const int row = koff + (nt + q) * 8 + gid;
                const uint4 B0 = *(const uint4*)&w2[row * 36 + tI * 8];
                const uint4 B1 = *(const uint4*)&w2[row * 36 + tI * 8 + 4];
                mma_f16(c[q][0], c[q][1], c[q][2], c[q][3],
                        A[0][0], A[0][1], A[0][2], A[0][3], B0.x, B0.y);
                mma_f16(c[q][0], c[q][1], c[q][2], c[q][3],
                        A[1][0], A[1][1], A[1][2], A[1][3], B0.z, B0.w);
                mma_f16(c[q][0], c[q][1], c[q][2], c[q][3],
                        A[2][0], A[2][1], A[2][2], A[2][3], B1.x, B1.y);
                mma_f16(c[q][0], c[q][1], c[q][2], c[q][3],
                        A[3][0], A[3][1], A[3][2], A[3][3], B1.z, B1.w);
            }
#pragma unroll
            for (int q = 0; q < 4; q++) {
                const int cb = koff + (nt + q) * 8 + 2 * tI;
                const float w0 = wsq_s[cb], w1 = wsq_s[cb + 1];
                const float d00 = __fmaf_rn(-2.f, c[q][0], w0);
                const float d01 = __fmaf_rn(-2.f, c[q][1], w1);
                const float d10 = __fmaf_rn(-2.f, c[q][2], w0);
                const float d11 = __fmaf_rn(-2.f, c[q][3], w1);
                if (d00 < best0) { sec0 = best0; best0 = d00; bi0 = cb; }
                else if (d00 < sec0) sec0 = d00;
                if (d01 < best0) { sec0 = best0; best0 = d01; bi0 = cb + 1; }
                else if (d01 < sec0) sec0 = d01;
                if (d10 < best1) { sec1 = best1; best1 = d10; bi1 = cb; }
                else if (d10 < sec1) sec1 = d10;
                if (d11 < best1) { sec1 = best1; best1 = d11; bi1 = cb + 1; }
                else if (d11 < sec1) sec1 = d11;
            }
        }

#pragma unroll
        for (int m = 1; m <= 2; m <<= 1) {
            float ob = __shfl_xor_sync(0xffffffffu, best0, m);
            float os = __shfl_xor_sync(0xffffffffu, sec0,  m);
            int  obi = __shfl_xor_sync(0xffffffffu, bi0,   m);
            if (ob < best0 || (ob == best0 && obi < bi0)) { sec0 = fminf(best0, os); best0 = ob; bi0 = obi; }
            else sec0 = fminf(sec0, ob);
            ob  = __shfl_xor_sync(0xffffffffu, best1, m);
            os  = __shfl_xor_sync(0xffffffffu, sec1,  m);
            obi = __shfl_xor_sync(0xffffffffu, bi1,   m);
            if (ob < best1 || (ob == best1 && obi < bi1)) { sec1 = fminf(best1, os); best1 = ob; bi1 = obi; }
            else sec1 = fminf(sec1, ob);
        }
        if (tI == 0) {
            rb[half * 64 + r0] = best0; rs[half * 64 + r0] = sec0; ri[half * 64 + r0] = bi0;
            rb[half * 64 + r1] = best1; rs[half * 64 + r1] = sec1; ri[half * 64 + r1] = bi1;
        }
        __syncthreads();

        if (tid < TILE_M) {
            const int p = tid;
            const float b1v = rb[p],      s1v = rs[p];
            const float b2v = rb[64 + p], s2v = rs[64 + p];
            const int   i1v = ri[p],      i2v = ri[64 + p];
            float bb, ss; int ii;
            if (b2v < b1v || (b2v == b1v && i2v < i1v)) { bb = b2v; ii = i2v; }
            else { bb = b1v; ii = i1v; }
            ss = fminf(fminf(s1v, s2v), fmaxf(b1v, b2v));

            out_idx[n0 + p] = (float)ii;
            res_i[p] = ii;

            const float S1 = s1h[p] + s1h[64 + p] + s1h[128 + p] + s1h[192 + p];
            const bool flag = (__fsub_rn(ss, bb) < __fmaf_rn(1e-5f, S1, 4e-5f));
            res_f[p] = flag;
            const unsigned m = __ballot_sync(0xffffffffu, flag);
            if (m) {
                const int lane2 = tid & 31;
                const int leader = __ffs(m) - 1;
                int base = 0;
                if (lane2 == leader) base = atomicAdd(&g_nflag, __popc(m));
                base = __shfl_sync(0xffffffffu, base, leader);
                if (flag) g_flag[base + __popc(m & ((1u << lane2) - 1u))] = n0 + p;
            }
        }
        __syncthreads();

        if (tid < 2 * TILE_M) {
            const int p  = tid >> 1;
            const int dh = (tid & 1) * 32;
            if (!res_f[p]) {
                const int n  = n0 + p;
                const int ii = res_i[p];
                const float*  xp = x     + (size_t)b * DD * HW + hw0 + p;
                float*        qp = out_q + (size_t)b * DD * HW + hw0 + p;
                const float4* wr = (const float4*)(w + (size_t)ii * DD + dh);
#pragma unroll
                for (int j = 0; j < 8; j++) {
                    const float4 wv = __ldg(wr + j);
                    const int d0i = dh + 4 * j;
                    const float xv0 = xp[(size_t)(d0i + 0) * HW];
                    const float xv1 = xp[(size_t)(d0i + 1) * HW];
                    const float xv2 = xp[(size_t)(d0i + 2) * HW];
                    const float xv3 = xp[(size_t)(d0i + 3) * HW];
                    const float d0 = __fsub_rn(wv.x, xv0);
                    const float d1 = __fsub_rn(wv.y, xv1);
                    const float d2 = __fsub_rn(wv.z, xv2);
                    const float d3 = __fsub_rn(wv.w, xv3);
                    qp[(size_t)(d0i + 0) * HW] = __fadd_rn(xv0, d0);
                    qp[(size_t)(d0i + 1) * HW] = __fadd_rn(xv1, d1);
                    qp[(size_t)(d0i + 2) * HW] = __fadd_rn(xv2, d2);
                    qp[(size_t)(d0i + 3) * HW] = __fadd_rn(xv3, d3);
                    loss_acc = fmaf(d0, d0, loss_acc); loss_acc = fmaf(d1, d1, loss_acc);
                    loss_acc = fmaf(d2, d2, loss_acc); loss_acc = fmaf(d3, d3, loss_acc);
                }
                if ((tid & 1) == 0) out_enc[(size_t)n * KC + ii] = 1.0f;
            }
        }
        __syncthreads();
    }

    float s = loss_acc;
#pragma unroll
    for (int off = 16; off; off >>= 1) s += __shfl_down_sync(0xffffffffu, s, off);
    __shared__ float sred[8];
    if ((tid & 31) == 0) sred[tid >> 5] = s;
    __syncthreads();
    if (tid < 8) {
        float v = sred[tid];
#pragma unroll
        for (int off = 4; off; off >>= 1) v += __shfl_down_sync(0xffu, v, off);
        if (tid == 0 && v != 0.f) atomicAdd(losssum, (double)v);
    }
}

// ---------------------------------------------------------------------------
// K2: bit-exact fallback — vectorized LDS.128 (stride-68 w rows), 2-way code
// ILP per lane; q / enc / loss for flagged pixels + fused finalize.
// ---------------------------------------------------------------------------
#define FB_WS   68   // float stride per code row (float4-aligned, conflict-free)
__global__ void __launch_bounds__(256, 1)
vq_fallback(const float* __restrict__ x, const float* __restrict__ w,
            float* __restrict__ out_idx, float* __restrict__ out_q,
            float* __restrict__ out_enc, double* __restrict__ losssum,
            float* __restrict__ out_loss)
{
    extern __shared__ char smc[];
    float* w_s   = (float*)smc;                               // [512*68]
    float* wsq_s = (float*)(smc + KC * FB_WS * 4);            // [512]
    float* xrow  = (float*)(smc + KC * FB_WS * 4 + KC * 4);   // [8][64]
    const int tid = threadIdx.x, wid = tid >> 5, lane = tid & 31;
    const int nflag = g_nflag;

    if (blockIdx.x * 8 < nflag) {
        for (int i = tid; i < KC * 16; i += 256) {   // float4 granularity
            const int k = i >> 4, m = i & 15;
            *(float4*)&w_s[k * FB_WS + 4 * m] = *(const float4*)(w + (size_t)k * DD + 4 * m);
        }
        __syncthreads();
        // wsq via the bit-exact tree (2 codes per thread)
#pragma unroll
        for (int c = 0; c < 2; c++) {
            const int k = tid + c * 256;
            float v[DD];
#pragma unroll
            for (int d = 0; d < DD; d++) v[d] = w_s[k * FB_WS + d];
            wsq_s[k] = sumsq_tree64(v);
        }
        __syncthreads();

        for (int f = blockIdx.x * 8 + wid; f < nflag; f += gridDim.x * 8) {
            const int n  = g_flag[f];
            const int b  = n >> 12, hw = n & 4095;
            const float* xp = x + (size_t)b * DD * HW + hw;
            xrow[wid * 64 + lane]      = xp[(size_t)lane * HW];
            xrow[wid * 64 + lane + 32] = xp[(size_t)(lane + 32) * HW];
            __syncwarp();
            float pa = __fmul_rn(xrow[wid * 64 + 2 * lane],     xrow[wid * 64 + 2 * lane]);
            float pb = __fmul_rn(xrow[wid * 64 + 2 * lane + 1], xrow[wid * 64 + 2 * lane + 1]);
            float pt = __fadd_rn(pa, pb);
#pragma unroll
            for (int off = 16; off >= 1; off >>= 1) {
                const float q = __shfl_down_sync(0xffffffffu, pt, off);
                pt = __fadd_rn(pt, q);
            }
            const float xsq = __shfl_sync(0xffffffffu, pt, 0);

            float bd = 3.4e38f; int bk = 0;
#pragma unroll 1
            for (int j = 0; j < 16; j += 2) {   // 2 codes per lane concurrently
                const int k0 = lane + 32 * j;
                const int k1 = k0 + 32;
                float dot0 = 0.f, dot1 = 0.f;
#pragma unroll
                for (int m = 0; m < 16; m++) {
                    const float4 xv = *(const float4*)&xrow[wid * 64 + 4 * m];  // broadcast
                    const float4 w0 = *(const float4*)&w_s[k0 * FB_WS + 4 * m];
                    const float4 w1 = *(const float4*)&w_s[k1 * FB_WS + 4 * m];
                    // sequential in d per code chain (bit-exact)
                    dot0 = __fmaf_rn(xv.x, w0.x, dot0);
                    dot1 = __fmaf_rn(xv.x, w1.x, dot1);
                    dot0 = __fmaf_rn(xv.y, w0.y, dot0);
                    dot1 = __fmaf_rn(xv.y, w1.y, dot1);
                    dot0 = __fmaf_rn(xv.z, w0.z, dot0);
                    dot1 = __fmaf_rn(xv.z, w1.z, dot1);
                    dot0 = __fmaf_rn(xv.w, w0.w, dot0);
                    dot1 = __fmaf_rn(xv.w, w1.w, dot1);
                }
                const float dist0 = __fsub_rn(__fadd_rn(xsq, wsq_s[k0]), __fadd_rn(dot0, dot0));
                const float dist1 = __fsub_rn(__fadd_rn(xsq, wsq_s[k1]), __fadd_rn(dot1, dot1));
                if (dist0 < bd) { bd = dist0; bk = k0; }   // k ascending per lane
                if (dist1 < bd) { bd = dist1; bk = k1; }
            }
#pragma unroll
            for (int off = 16; off >= 1; off >>= 1) {
                const float od = __shfl_down_sync(0xffffffffu, bd, off);
                const int   ok = __shfl_down_sync(0xffffffffu, bk, off);
                if (od < bd || (od == bd && ok < bk)) { bd = od; bk = ok; }
            }
            bk = __shfl_sync(0xffffffffu, bk, 0);

            float* qp = out_q + (size_t)b * DD * HW + hw;
            const float xv0 = xrow[wid * 64 + lane];
            const float xv1 = xrow[wid * 64 + lane + 32];
            const float wv0 = w_s[bk * FB_WS + lane];
            const float wv1 = w_s[bk * FB_WS + lane + 32];
            const float d0  = __fsub_rn(wv0, xv0);
            const float d1  = __fsub_rn(wv1, xv1);
            qp[(size_t)lane * HW]        = __fadd_rn(xv0, d0);
            qp[(size_t)(lane + 32) * HW] = __fadd_rn(xv1, d1);
            float ls = fmaf(d1, d1, __fmul_rn(d0, d0));
#pragma unroll
            for (int off = 16; off >= 1; off >>= 1)
                ls += __shfl_down_sync(0xffffffffu, ls, off);
            if (lane == 0) {
                out_idx[n] = (float)bk;
                out_enc[(size_t)n * KC + bk] = 1.0f;
                atomicAdd(losssum, (double)ls);
            }
            __syncwarp();
        }
    }
    __syncthreads();
    if (tid == 0) {
        __threadfence();
        const int old = atomicAdd(&g_done, 1);
        if (old == (int)gridDim.x - 1) {
            __threadfence();
            out_loss[0] = (float)(2.0 * (*losssum) / (double)XNUM);
            g_done = 0;
        }
    }
}

// ---------------------------------------------------------------------------
extern "C" void kernel_launch(void* const* d_in, const int* in_sizes, int n_in,
                              void* d_out, int out_size)
{
    const float* x = (const float*)d_in[0];   // [32, 64, 64, 64] NCHW
    const float* w = (const float*)d_in[1];   // [512, 64]

    float* out      = (float*)d_out;
    float* out_loss = out;
    float* out_q    = out + 1;
    float* out_enc  = out + 1 + (size_t)XNUM;
    float* out_idx  = out + 1 + (size_t)XNUM + (size_t)NPIX * KC;

    double* loss_ptr  = nullptr;
    int*    nflag_ptr = nullptr;
    cudaGetSymbolAddress((void**)&loss_ptr,  g_losssum);
    cudaGetSymbolAddress((void**)&nflag_ptr, g_nflag);

    const int smem_fb = KC * FB_WS * 4 + KC * 4 + 8 * DD * 4;
    cudaFuncSetAttribute(vq_mma_filter, cudaFuncAttributeMaxDynamicSharedMemorySize, SM_TOT);
    cudaFuncSetAttribute(vq_fallback,   cudaFuncAttributeMaxDynamicSharedMemorySize, smem_fb);

    cudaMemsetAsync(loss_ptr,  0, sizeof(double), 0);
    cudaMemsetAsync(nflag_ptr, 0, sizeof(int), 0);

    vq_mma_filter<<<GRID_F, 256, SM_TOT>>>(x, w, out_idx, out_q, out_enc, loss_ptr);
    vq_fallback  <<<148, 256, smem_fb>>>(x, w, out_idx, out_q, out_enc, loss_ptr, out_loss);
}